// round 2
// baseline (speedup 1.0000x reference)
#include <cuda_runtime.h>
#include <math.h>

#define N_NODES 100000
#define NUM_GRAPHS 128
#define H1 4
#define C1 48
#define F1 192   // H1*C1
#define C2 96
#define D_IN 128
#define NEG_SLOPE 0.2f
#define E_MAX 1750000   // raw edges (1.6M) + self loops (100k) with slack

// ---------------- scratch (device globals; no allocation) ----------------
__device__ float g_h1[N_NODES * F1];      // x @ W1
__device__ float g_agg1[N_NODES * F1];    // layer1 aggregate -> relu in place
__device__ float g_asrc1[N_NODES * H1];
__device__ float g_adst1[N_NODES * H1];
__device__ float g_m1[N_NODES * H1];
__device__ float g_den1[N_NODES * H1];
__device__ float g_h2[N_NODES * C2];      // h1r @ W2
__device__ float g_agg2[N_NODES * C2];
__device__ float g_asrc2[N_NODES];
__device__ float g_adst2[N_NODES];
__device__ float g_m2[N_NODES];
__device__ float g_den2[N_NODES];
__device__ float g_pool[NUM_GRAPHS * C2];
__device__ float g_cnt[NUM_GRAPHS];
__device__ int g_src[E_MAX];
__device__ int g_dst[E_MAX];
__device__ int g_batch[N_NODES];
__device__ int g_is64;

// ---------------- helpers ----------------
__device__ __forceinline__ void atomicMaxFloat(float* addr, float value) {
    if (value >= 0.0f) {
        atomicMax((int*)addr, __float_as_int(value));
    } else {
        atomicMin((unsigned int*)addr, __float_as_uint(value));
    }
}

__device__ __forceinline__ float leaky(float s) {
    return s > 0.0f ? s : NEG_SLOPE * s;
}

// ---------------- dtype sniff: int64 vs int32 index buffers ----------------
// If the buffer is int64 (little-endian), the high word of every entry is 0
// (indices < 2^17). If int32, those words are edge indices (nonzero w.h.p.).
__global__ void sniff_kernel(const unsigned int* __restrict__ w) {
    __shared__ int any_nonzero;
    if (threadIdx.x == 0) any_nonzero = 0;
    __syncthreads();
    for (int i = threadIdx.x; i < 256; i += blockDim.x) {
        if (w[2 * i + 1] != 0u) any_nonzero = 1;
    }
    __syncthreads();
    if (threadIdx.x == 0) g_is64 = (any_nonzero == 0) ? 1 : 0;
}

// decode edge_index + self loops into int32 arrays
__global__ void decode_edges(const void* __restrict__ ei_raw, int E0) {
    int e = blockIdx.x * blockDim.x + threadIdx.x;
    int Etot = E0 + N_NODES;
    if (e >= Etot) return;
    if (e < E0) {
        if (g_is64) {
            const long long* p = (const long long*)ei_raw;
            g_src[e] = (int)p[e];
            g_dst[e] = (int)p[E0 + e];
        } else {
            const int* p = (const int*)ei_raw;
            g_src[e] = p[e];
            g_dst[e] = p[E0 + e];
        }
    } else {
        int n = e - E0;
        g_src[e] = n;
        g_dst[e] = n;
    }
}

__global__ void decode_batch(const void* __restrict__ b_raw) {
    int n = blockIdx.x * blockDim.x + threadIdx.x;
    if (n >= N_NODES) return;
    if (g_is64) {
        g_batch[n] = (int)((const long long*)b_raw)[n];
    } else {
        g_batch[n] = ((const int*)b_raw)[n];
    }
}

// ---------------- init ----------------
__global__ void init_kernel() {
    long long i = (long long)blockIdx.x * blockDim.x + threadIdx.x;
    long long stride = (long long)gridDim.x * blockDim.x;
    for (long long k = i; k < (long long)N_NODES * F1; k += stride) g_agg1[k] = 0.0f;
    for (long long k = i; k < (long long)N_NODES * C2; k += stride) g_agg2[k] = 0.0f;
    for (long long k = i; k < (long long)N_NODES * H1; k += stride) {
        g_m1[k] = -INFINITY;
        g_den1[k] = 0.0f;
    }
    for (long long k = i; k < (long long)N_NODES; k += stride) {
        g_m2[k] = -INFINITY;
        g_den2[k] = 0.0f;
    }
    for (long long k = i; k < (long long)(NUM_GRAPHS * C2); k += stride) g_pool[k] = 0.0f;
    for (long long k = i; k < (long long)NUM_GRAPHS; k += stride) g_cnt[k] = 0.0f;
}

// ---------------- tiled SGEMM: C[M,N] = A[M,K] @ B[K,N] (row major) ----------------
#define BM 64
#define BN 64
#define BKK 32
__global__ void sgemm_kernel(const float* __restrict__ A, const float* __restrict__ B,
                             float* __restrict__ C, int M, int N, int K) {
    __shared__ float As[BM][BKK + 1];
    __shared__ float Bs[BKK][BN];
    int tid = threadIdx.x;          // 256 threads
    int tx = tid & 15;
    int ty = tid >> 4;
    int row0 = blockIdx.y * BM;
    int col0 = blockIdx.x * BN;

    float acc[4][4];
#pragma unroll
    for (int i = 0; i < 4; i++)
#pragma unroll
        for (int j = 0; j < 4; j++) acc[i][j] = 0.0f;

    for (int k0 = 0; k0 < K; k0 += BKK) {
#pragma unroll
        for (int i = 0; i < 8; i++) {  // 64*32/256 = 8 per thread
            int idx = tid + i * 256;
            int r = idx >> 5, c = idx & 31;
            int gr = row0 + r;
            As[r][c] = (gr < M) ? A[(size_t)gr * K + k0 + c] : 0.0f;
        }
#pragma unroll
        for (int i = 0; i < 8; i++) {  // 32*64/256 = 8 per thread
            int idx = tid + i * 256;
            int r = idx >> 6, c = idx & 63;
            int gc = col0 + c;
            Bs[r][c] = (gc < N) ? B[(size_t)(k0 + r) * N + gc] : 0.0f;
        }
        __syncthreads();
#pragma unroll
        for (int k = 0; k < BKK; k++) {
            float a[4], b[4];
#pragma unroll
            for (int i = 0; i < 4; i++) a[i] = As[ty * 4 + i][k];
#pragma unroll
            for (int j = 0; j < 4; j++) b[j] = Bs[k][tx * 4 + j];
#pragma unroll
            for (int i = 0; i < 4; i++)
#pragma unroll
                for (int j = 0; j < 4; j++) acc[i][j] += a[i] * b[j];
        }
        __syncthreads();
    }
#pragma unroll
    for (int i = 0; i < 4; i++) {
        int gr = row0 + ty * 4 + i;
        if (gr >= M) continue;
#pragma unroll
        for (int j = 0; j < 4; j++) {
            int gc = col0 + tx * 4 + j;
            if (gc < N) C[(size_t)gr * N + gc] = acc[i][j];
        }
    }
}

// ---------------- attention scalars ----------------
__global__ void attn1_kernel(const float* __restrict__ a_src, const float* __restrict__ a_dst) {
    int idx = blockIdx.x * blockDim.x + threadIdx.x;  // node*4 + head
    if (idx >= N_NODES * H1) return;
    int n = idx >> 2, h = idx & 3;
    const float* hp = &g_h1[(size_t)n * F1 + h * C1];
    const float* ws = &a_src[h * C1];
    const float* wd = &a_dst[h * C1];
    float ss = 0.0f, sd = 0.0f;
#pragma unroll
    for (int j = 0; j < C1; j++) {
        float v = hp[j];
        ss += v * ws[j];
        sd += v * wd[j];
    }
    g_asrc1[idx] = ss;
    g_adst1[idx] = sd;
}

__global__ void attn2_kernel(const float* __restrict__ a_src, const float* __restrict__ a_dst) {
    int w = (blockIdx.x * blockDim.x + threadIdx.x) >> 5;
    int lane = threadIdx.x & 31;
    if (w >= N_NODES) return;
    const float* hp = &g_h2[(size_t)w * C2];
    float ss = 0.0f, sd = 0.0f;
#pragma unroll
    for (int k = 0; k < 3; k++) {
        int j = lane + 32 * k;
        float v = hp[j];
        ss += v * a_src[j];
        sd += v * a_dst[j];
    }
#pragma unroll
    for (int o = 16; o > 0; o >>= 1) {
        ss += __shfl_down_sync(0xffffffffu, ss, o);
        sd += __shfl_down_sync(0xffffffffu, sd, o);
    }
    if (lane == 0) {
        g_asrc2[w] = ss;
        g_adst2[w] = sd;
    }
}

// ---------------- layer 1 edge passes ----------------
__global__ void edge_max1(int Etot) {
    int idx = blockIdx.x * blockDim.x + threadIdx.x;
    if (idx >= Etot * H1) return;
    int e = idx >> 2, h = idx & 3;
    int src = g_src[e], dst = g_dst[e];
    float s = leaky(g_asrc1[src * H1 + h] + g_adst1[dst * H1 + h]);
    atomicMaxFloat(&g_m1[dst * H1 + h], s);
}

__global__ void edge_sum1(int Etot) {
    int idx = blockIdx.x * blockDim.x + threadIdx.x;
    if (idx >= Etot * H1) return;
    int e = idx >> 2, h = idx & 3;
    int src = g_src[e], dst = g_dst[e];
    float s = leaky(g_asrc1[src * H1 + h] + g_adst1[dst * H1 + h]);
    atomicAdd(&g_den1[dst * H1 + h], __expf(s - g_m1[dst * H1 + h]));
}

__global__ void edge_agg1(int Etot) {
    int gw = (blockIdx.x * blockDim.x + threadIdx.x) >> 5;
    int lane = threadIdx.x & 31;
    if (gw >= Etot) return;
    int src = g_src[gw], dst = g_dst[gw];
    float alpha = 0.0f;
    if (lane < H1) {
        int h = lane;
        float s = leaky(g_asrc1[src * H1 + h] + g_adst1[dst * H1 + h]);
        alpha = __expf(s - g_m1[dst * H1 + h]) / g_den1[dst * H1 + h];
    }
    const float* hp = &g_h1[(size_t)src * F1];
    float* op = &g_agg1[(size_t)dst * F1];
#pragma unroll
    for (int k = 0; k < 6; k++) {
        int c = lane + 32 * k;
        float al = __shfl_sync(0xffffffffu, alpha, c / C1);
        atomicAdd(&op[c], hp[c] * al);
    }
}

__global__ void relu_bias1(const float* __restrict__ b1) {
    int idx = blockIdx.x * blockDim.x + threadIdx.x;
    if (idx >= N_NODES * F1) return;
    int c = idx % F1;
    g_agg1[idx] = fmaxf(g_agg1[idx] + b1[c], 0.0f);
}

// ---------------- layer 2 edge passes ----------------
__global__ void edge_max2(int Etot) {
    int e = blockIdx.x * blockDim.x + threadIdx.x;
    if (e >= Etot) return;
    int src = g_src[e], dst = g_dst[e];
    float s = leaky(g_asrc2[src] + g_adst2[dst]);
    atomicMaxFloat(&g_m2[dst], s);
}

__global__ void edge_sum2(int Etot) {
    int e = blockIdx.x * blockDim.x + threadIdx.x;
    if (e >= Etot) return;
    int src = g_src[e], dst = g_dst[e];
    float s = leaky(g_asrc2[src] + g_adst2[dst]);
    atomicAdd(&g_den2[dst], __expf(s - g_m2[dst]));
}

__global__ void edge_agg2(int Etot) {
    int gw = (blockIdx.x * blockDim.x + threadIdx.x) >> 5;
    int lane = threadIdx.x & 31;
    if (gw >= Etot) return;
    int src = g_src[gw], dst = g_dst[gw];
    float alpha = 0.0f;
    if (lane == 0) {
        float s = leaky(g_asrc2[src] + g_adst2[dst]);
        alpha = __expf(s - g_m2[dst]) / g_den2[dst];
    }
    alpha = __shfl_sync(0xffffffffu, alpha, 0);
    const float* hp = &g_h2[(size_t)src * C2];
    float* op = &g_agg2[(size_t)dst * C2];
#pragma unroll
    for (int k = 0; k < 3; k++) {
        int c = lane + 32 * k;
        atomicAdd(&op[c], hp[c] * alpha);
    }
}

// ---------------- relu + bias + global mean pool ----------------
__global__ void pool_kernel(const float* __restrict__ b2) {
    int idx = blockIdx.x * blockDim.x + threadIdx.x;
    if (idx < N_NODES * C2) {
        int n = idx / C2;
        int c = idx - n * C2;
        float v = fmaxf(g_agg2[idx] + b2[c], 0.0f);
        atomicAdd(&g_pool[g_batch[n] * C2 + c], v);
    }
    if (idx < N_NODES) {
        atomicAdd(&g_cnt[g_batch[idx]], 1.0f);
    }
}

// ---------------- final MLP: one block per graph ----------------
__global__ void mlp_kernel(const float* __restrict__ fc1_w, const float* __restrict__ fc1_b,
                           const float* __restrict__ fc2_w, const float* __restrict__ fc2_b,
                           float* __restrict__ out) {
    __shared__ float p[C2];
    __shared__ float z[192];
    int g = blockIdx.x;
    int t = threadIdx.x;  // 192 threads
    float inv = 1.0f / fmaxf(g_cnt[g], 1.0f);
    if (t < C2) p[t] = g_pool[g * C2 + t] * inv;
    __syncthreads();
    float acc = fc1_b[t];
#pragma unroll
    for (int k = 0; k < C2; k++) acc += p[k] * fc1_w[k * 192 + t];
    z[t] = fmaxf(acc, 0.0f);
    __syncthreads();
    if (t < C2) {
        float o = fc2_b[t];
#pragma unroll
        for (int k = 0; k < 192; k++) o += z[k] * fc2_w[k * C2 + t];
        out[g * C2 + t] = o;
    }
}

// ---------------- host launch ----------------
extern "C" void kernel_launch(void* const* d_in, const int* in_sizes, int n_in,
                              void* d_out, int out_size) {
    const float* x = (const float*)d_in[0];
    const void* ei_raw = d_in[1];
    const void* batch_raw = d_in[2];
    const float* W1 = (const float*)d_in[3];
    const float* a_src1 = (const float*)d_in[4];
    const float* a_dst1 = (const float*)d_in[5];
    const float* b1 = (const float*)d_in[6];
    const float* W2 = (const float*)d_in[7];
    const float* a_src2 = (const float*)d_in[8];
    const float* a_dst2 = (const float*)d_in[9];
    const float* b2 = (const float*)d_in[10];
    const float* fc1_w = (const float*)d_in[11];
    const float* fc1_b = (const float*)d_in[12];
    const float* fc2_w = (const float*)d_in[13];
    const float* fc2_b = (const float*)d_in[14];
    float* out = (float*)d_out;

    int E0 = in_sizes[1] / 2;        // raw edges (element count is dtype-agnostic)
    int Etot = E0 + N_NODES;         // + self loops

    float *h1p, *agg1p, *h2p;
    cudaGetSymbolAddress((void**)&h1p, g_h1);
    cudaGetSymbolAddress((void**)&agg1p, g_agg1);
    cudaGetSymbolAddress((void**)&h2p, g_h2);

    // dtype sniff + decode indices to int32
    sniff_kernel<<<1, 256>>>((const unsigned int*)ei_raw);
    decode_edges<<<(Etot + 255) / 256, 256>>>(ei_raw, E0);
    decode_batch<<<(N_NODES + 255) / 256, 256>>>(batch_raw);

    init_kernel<<<2048, 256>>>();

    // layer 1
    {
        dim3 grid((F1 + BN - 1) / BN, (N_NODES + BM - 1) / BM);
        sgemm_kernel<<<grid, 256>>>(x, W1, h1p, N_NODES, F1, D_IN);
    }
    attn1_kernel<<<(N_NODES * H1 + 255) / 256, 256>>>(a_src1, a_dst1);
    edge_max1<<<(Etot * H1 + 255) / 256, 256>>>(Etot);
    edge_sum1<<<(Etot * H1 + 255) / 256, 256>>>(Etot);
    edge_agg1<<<(Etot + 7) / 8, 256>>>(Etot);  // warp per edge
    relu_bias1<<<(N_NODES * F1 + 255) / 256, 256>>>(b1);

    // layer 2
    {
        dim3 grid((C2 + BN - 1) / BN, (N_NODES + BM - 1) / BM);
        sgemm_kernel<<<grid, 256>>>(agg1p, W2, h2p, N_NODES, C2, F1);
    }
    attn2_kernel<<<(N_NODES * 32 + 255) / 256, 256>>>(a_src2, a_dst2);
    edge_max2<<<(Etot + 255) / 256, 256>>>(Etot);
    edge_sum2<<<(Etot + 255) / 256, 256>>>(Etot);
    edge_agg2<<<(Etot + 7) / 8, 256>>>(Etot);  // warp per edge

    // pool + MLP
    pool_kernel<<<(N_NODES * C2 + 255) / 256, 256>>>(b2);
    mlp_kernel<<<NUM_GRAPHS, 192>>>(fc1_w, fc1_b, fc2_w, fc2_b, out);
}

// round 3
// speedup vs baseline: 1.7705x; 1.7705x over previous
#include <cuda_runtime.h>
#include <math.h>

#define N_NODES 100000
#define NUM_GRAPHS 128
#define H1 4
#define C1 48
#define F1 192   // H1*C1
#define C2 96
#define D_IN 128
#define NEG_SLOPE 0.2f
#define E_MAX 1750000   // raw edges (1.6M) + self loops (100k) with slack

// ---------------- scratch (device globals; no allocation) ----------------
__device__ float g_h1[N_NODES * F1];      // x @ W1
__device__ float g_h1r[N_NODES * F1];     // layer1 output (relu'd)
__device__ float g_asrc1[N_NODES * H1];
__device__ float g_adst1[N_NODES * H1];
__device__ float g_h2[N_NODES * C2];      // h1r @ W2
__device__ float g_asrc2[N_NODES];
__device__ float g_adst2[N_NODES];
__device__ float g_pool[NUM_GRAPHS * C2];
__device__ float g_cnt[NUM_GRAPHS];
__device__ int g_src[E_MAX];
__device__ int g_dst[E_MAX];
__device__ int g_batch[N_NODES];
__device__ int g_is64;
// CSR (sorted by dst)
__device__ int g_deg[N_NODES];
__device__ int g_off[N_NODES + 1];
__device__ int g_cur[N_NODES];
__device__ int g_csr_src[E_MAX];
__device__ float g_p[E_MAX * H1];         // per-edge exp scores (layer1: 4/edge, layer2: 1/edge)

__device__ __forceinline__ float leaky(float s) {
    return s > 0.0f ? s : NEG_SLOPE * s;
}

// ---------------- init (zero counters only) ----------------
__global__ void init_kernel() {
    int i = blockIdx.x * blockDim.x + threadIdx.x;
    int stride = gridDim.x * blockDim.x;
    for (int k = i; k < N_NODES; k += stride) g_deg[k] = 0;
    for (int k = i; k < NUM_GRAPHS * C2; k += stride) g_pool[k] = 0.0f;
    for (int k = i; k < NUM_GRAPHS; k += stride) g_cnt[k] = 0.0f;
}

// ---------------- dtype sniff: int64 vs int32 index buffers ----------------
__global__ void sniff_kernel(const unsigned int* __restrict__ w) {
    __shared__ int any_nonzero;
    if (threadIdx.x == 0) any_nonzero = 0;
    __syncthreads();
    for (int i = threadIdx.x; i < 256; i += blockDim.x) {
        if (w[2 * i + 1] != 0u) any_nonzero = 1;
    }
    __syncthreads();
    if (threadIdx.x == 0) g_is64 = (any_nonzero == 0) ? 1 : 0;
}

// decode edge_index + self loops into int32 arrays; fused degree histogram
__global__ void decode_edges(const void* __restrict__ ei_raw, int E0) {
    int e = blockIdx.x * blockDim.x + threadIdx.x;
    int Etot = E0 + N_NODES;
    if (e >= Etot) return;
    int src, dst;
    if (e < E0) {
        if (g_is64) {
            const long long* p = (const long long*)ei_raw;
            src = (int)p[e];
            dst = (int)p[E0 + e];
        } else {
            const int* p = (const int*)ei_raw;
            src = p[e];
            dst = p[E0 + e];
        }
    } else {
        src = dst = e - E0;  // self loop
    }
    g_src[e] = src;
    g_dst[e] = dst;
    atomicAdd(&g_deg[dst], 1);
}

__global__ void decode_batch(const void* __restrict__ b_raw) {
    int n = blockIdx.x * blockDim.x + threadIdx.x;
    if (n >= N_NODES) return;
    int b = g_is64 ? (int)((const long long*)b_raw)[n] : ((const int*)b_raw)[n];
    g_batch[n] = b;
    atomicAdd(&g_cnt[b], 1.0f);
}

// ---------------- single-block exclusive scan over degrees ----------------
__global__ void scan_kernel() {
    __shared__ int part[1024];
    int t = threadIdx.x;
    const int CH = (N_NODES + 1023) / 1024;
    int lo = t * CH, hi = min(lo + CH, N_NODES);
    int s = 0;
    for (int i = lo; i < hi; i++) s += g_deg[i];
    part[t] = s;
    __syncthreads();
    for (int o = 1; o < 1024; o <<= 1) {
        int v = (t >= o) ? part[t - o] : 0;
        __syncthreads();
        part[t] += v;
        __syncthreads();
    }
    int base = (t > 0) ? part[t - 1] : 0;
    for (int i = lo; i < hi; i++) {
        g_off[i] = base;
        g_cur[i] = base;
        base += g_deg[i];
    }
    if (t == 1023) g_off[N_NODES] = part[1023];
}

__global__ void scatter_kernel(int Etot) {
    int e = blockIdx.x * blockDim.x + threadIdx.x;
    if (e >= Etot) return;
    int pos = atomicAdd(&g_cur[g_dst[e]], 1);
    g_csr_src[pos] = g_src[e];
}

// ---------------- tiled SGEMM: C[M,N] = A[M,K] @ B[K,N] (row major) ----------------
#define BM 64
#define BN 64
#define BKK 32
__global__ void sgemm_kernel(const float* __restrict__ A, const float* __restrict__ B,
                             float* __restrict__ C, int M, int N, int K) {
    __shared__ float As[BM][BKK + 1];
    __shared__ float Bs[BKK][BN];
    int tid = threadIdx.x;          // 256 threads
    int tx = tid & 15;
    int ty = tid >> 4;
    int row0 = blockIdx.y * BM;
    int col0 = blockIdx.x * BN;

    float acc[4][4];
#pragma unroll
    for (int i = 0; i < 4; i++)
#pragma unroll
        for (int j = 0; j < 4; j++) acc[i][j] = 0.0f;

    for (int k0 = 0; k0 < K; k0 += BKK) {
#pragma unroll
        for (int i = 0; i < 8; i++) {
            int idx = tid + i * 256;
            int r = idx >> 5, c = idx & 31;
            int gr = row0 + r;
            As[r][c] = (gr < M) ? A[(size_t)gr * K + k0 + c] : 0.0f;
        }
#pragma unroll
        for (int i = 0; i < 8; i++) {
            int idx = tid + i * 256;
            int r = idx >> 6, c = idx & 63;
            int gc = col0 + c;
            Bs[r][c] = (gc < N) ? B[(size_t)(k0 + r) * N + gc] : 0.0f;
        }
        __syncthreads();
#pragma unroll
        for (int k = 0; k < BKK; k++) {
            float a[4], b[4];
#pragma unroll
            for (int i = 0; i < 4; i++) a[i] = As[ty * 4 + i][k];
#pragma unroll
            for (int j = 0; j < 4; j++) b[j] = Bs[k][tx * 4 + j];
#pragma unroll
            for (int i = 0; i < 4; i++)
#pragma unroll
                for (int j = 0; j < 4; j++) acc[i][j] += a[i] * b[j];
        }
        __syncthreads();
    }
#pragma unroll
    for (int i = 0; i < 4; i++) {
        int gr = row0 + ty * 4 + i;
        if (gr >= M) continue;
#pragma unroll
        for (int j = 0; j < 4; j++) {
            int gc = col0 + tx * 4 + j;
            if (gc < N) C[(size_t)gr * N + gc] = acc[i][j];
        }
    }
}

// ---------------- attention scalars ----------------
__global__ void attn1_kernel(const float* __restrict__ a_src, const float* __restrict__ a_dst) {
    int idx = blockIdx.x * blockDim.x + threadIdx.x;  // node*4 + head
    if (idx >= N_NODES * H1) return;
    int n = idx >> 2, h = idx & 3;
    const float* hp = &g_h1[(size_t)n * F1 + h * C1];
    const float* ws = &a_src[h * C1];
    const float* wd = &a_dst[h * C1];
    float ss = 0.0f, sd = 0.0f;
#pragma unroll
    for (int j = 0; j < C1; j++) {
        float v = hp[j];
        ss += v * ws[j];
        sd += v * wd[j];
    }
    g_asrc1[idx] = ss;
    g_adst1[idx] = sd;
}

__global__ void attn2_kernel(const float* __restrict__ a_src, const float* __restrict__ a_dst) {
    int w = (blockIdx.x * blockDim.x + threadIdx.x) >> 5;
    int lane = threadIdx.x & 31;
    if (w >= N_NODES) return;
    const float* hp = &g_h2[(size_t)w * C2];
    float ss = 0.0f, sd = 0.0f;
#pragma unroll
    for (int k = 0; k < 3; k++) {
        int j = lane + 32 * k;
        float v = hp[j];
        ss += v * a_src[j];
        sd += v * a_dst[j];
    }
#pragma unroll
    for (int o = 16; o > 0; o >>= 1) {
        ss += __shfl_down_sync(0xffffffffu, ss, o);
        sd += __shfl_down_sync(0xffffffffu, sd, o);
    }
    if (lane == 0) {
        g_asrc2[w] = ss;
        g_adst2[w] = sd;
    }
}

// ---------------- layer 1 fused: softmax + aggregate + bias + relu (warp/node) ----------------
__global__ void gat1_kernel(const float* __restrict__ b1) {
    int node = (blockIdx.x * blockDim.x + threadIdx.x) >> 5;
    int lane = threadIdx.x & 31;
    if (node >= N_NODES) return;
    int start = g_off[node], end = g_off[node + 1];

    float4 ad = *(const float4*)&g_adst1[node * H1];

    // pass A: exp scores + denominator
    float4 den = make_float4(0.f, 0.f, 0.f, 0.f);
    for (int idx = start + lane; idx < end; idx += 32) {
        int src = g_csr_src[idx];
        float4 as = *(const float4*)&g_asrc1[src * H1];
        float4 p;
        p.x = __expf(leaky(as.x + ad.x));
        p.y = __expf(leaky(as.y + ad.y));
        p.z = __expf(leaky(as.z + ad.z));
        p.w = __expf(leaky(as.w + ad.w));
        *(float4*)&g_p[(size_t)idx * 4] = p;
        den.x += p.x; den.y += p.y; den.z += p.z; den.w += p.w;
    }
#pragma unroll
    for (int o = 16; o > 0; o >>= 1) {
        den.x += __shfl_xor_sync(0xffffffffu, den.x, o);
        den.y += __shfl_xor_sync(0xffffffffu, den.y, o);
        den.z += __shfl_xor_sync(0xffffffffu, den.z, o);
        den.w += __shfl_xor_sync(0xffffffffu, den.w, o);
    }
    float inv0 = 1.0f / den.x, inv1 = 1.0f / den.y, inv2 = 1.0f / den.z, inv3 = 1.0f / den.w;

    // pass B: weighted aggregation
    float acc[6] = {0.f, 0.f, 0.f, 0.f, 0.f, 0.f};
    for (int idx = start; idx < end; idx++) {
        int src = g_csr_src[idx];                       // broadcast load
        float4 p4 = *(const float4*)&g_p[(size_t)idx * 4];  // broadcast load
        float a0 = p4.x * inv0, a1 = p4.y * inv1, a2 = p4.z * inv2, a3 = p4.w * inv3;
        const float* hp = &g_h1[(size_t)src * F1];
#pragma unroll
        for (int k = 0; k < 6; k++) {
            int c = k * 32 + lane;
            float al = (c < 48) ? a0 : (c < 96) ? a1 : (c < 144) ? a2 : a3;
            acc[k] += hp[c] * al;
        }
    }
#pragma unroll
    for (int k = 0; k < 6; k++) {
        int c = k * 32 + lane;
        g_h1r[(size_t)node * F1 + c] = fmaxf(acc[k] + b1[c], 0.0f);
    }
}

// ---------------- layer 2 fused: softmax + aggregate + bias + relu + pool (warp/node) ----------------
__global__ void gat2_kernel(const float* __restrict__ b2) {
    int node = (blockIdx.x * blockDim.x + threadIdx.x) >> 5;
    int lane = threadIdx.x & 31;
    if (node >= N_NODES) return;
    int start = g_off[node], end = g_off[node + 1];

    float ad = g_adst2[node];
    float den = 0.0f;
    for (int idx = start + lane; idx < end; idx += 32) {
        int src = g_csr_src[idx];
        float p = __expf(leaky(g_asrc2[src] + ad));
        g_p[idx] = p;
        den += p;
    }
#pragma unroll
    for (int o = 16; o > 0; o >>= 1) den += __shfl_xor_sync(0xffffffffu, den, o);
    float inv = 1.0f / den;

    float acc[3] = {0.f, 0.f, 0.f};
    for (int idx = start; idx < end; idx++) {
        int src = g_csr_src[idx];
        float alpha = g_p[idx] * inv;
        const float* hp = &g_h2[(size_t)src * C2];
#pragma unroll
        for (int k = 0; k < 3; k++) acc[k] += hp[k * 32 + lane] * alpha;
    }
    int gp = g_batch[node] * C2;
#pragma unroll
    for (int k = 0; k < 3; k++) {
        int c = k * 32 + lane;
        float v = fmaxf(acc[k] + b2[c], 0.0f);
        atomicAdd(&g_pool[gp + c], v);
    }
}

// ---------------- final MLP: one block per graph ----------------
__global__ void mlp_kernel(const float* __restrict__ fc1_w, const float* __restrict__ fc1_b,
                           const float* __restrict__ fc2_w, const float* __restrict__ fc2_b,
                           float* __restrict__ out) {
    __shared__ float p[C2];
    __shared__ float z[192];
    int g = blockIdx.x;
    int t = threadIdx.x;  // 192 threads
    float inv = 1.0f / fmaxf(g_cnt[g], 1.0f);
    if (t < C2) p[t] = g_pool[g * C2 + t] * inv;
    __syncthreads();
    float acc = fc1_b[t];
#pragma unroll
    for (int k = 0; k < C2; k++) acc += p[k] * fc1_w[k * 192 + t];
    z[t] = fmaxf(acc, 0.0f);
    __syncthreads();
    if (t < C2) {
        float o = fc2_b[t];
#pragma unroll
        for (int k = 0; k < 192; k++) o += z[k] * fc2_w[k * C2 + t];
        out[g * C2 + t] = o;
    }
}

// ---------------- host launch ----------------
extern "C" void kernel_launch(void* const* d_in, const int* in_sizes, int n_in,
                              void* d_out, int out_size) {
    const float* x = (const float*)d_in[0];
    const void* ei_raw = d_in[1];
    const void* batch_raw = d_in[2];
    const float* W1 = (const float*)d_in[3];
    const float* a_src1 = (const float*)d_in[4];
    const float* a_dst1 = (const float*)d_in[5];
    const float* b1 = (const float*)d_in[6];
    const float* W2 = (const float*)d_in[7];
    const float* a_src2 = (const float*)d_in[8];
    const float* a_dst2 = (const float*)d_in[9];
    const float* b2 = (const float*)d_in[10];
    const float* fc1_w = (const float*)d_in[11];
    const float* fc1_b = (const float*)d_in[12];
    const float* fc2_w = (const float*)d_in[13];
    const float* fc2_b = (const float*)d_in[14];
    float* out = (float*)d_out;

    int E0 = in_sizes[1] / 2;
    int Etot = E0 + N_NODES;

    float *h1p, *h1rp, *h2p;
    cudaGetSymbolAddress((void**)&h1p, g_h1);
    cudaGetSymbolAddress((void**)&h1rp, g_h1r);
    cudaGetSymbolAddress((void**)&h2p, g_h2);

    // graph preprocessing
    init_kernel<<<256, 256>>>();
    sniff_kernel<<<1, 256>>>((const unsigned int*)ei_raw);
    decode_edges<<<(Etot + 255) / 256, 256>>>(ei_raw, E0);
    decode_batch<<<(N_NODES + 255) / 256, 256>>>(batch_raw);
    scan_kernel<<<1, 1024>>>();
    scatter_kernel<<<(Etot + 255) / 256, 256>>>(Etot);

    // layer 1
    {
        dim3 grid((F1 + BN - 1) / BN, (N_NODES + BM - 1) / BM);
        sgemm_kernel<<<grid, 256>>>(x, W1, h1p, N_NODES, F1, D_IN);
    }
    attn1_kernel<<<(N_NODES * H1 + 255) / 256, 256>>>(a_src1, a_dst1);
    gat1_kernel<<<(N_NODES + 7) / 8, 256>>>(b1);

    // layer 2
    {
        dim3 grid((C2 + BN - 1) / BN, (N_NODES + BM - 1) / BM);
        sgemm_kernel<<<grid, 256>>>(h1rp, W2, h2p, N_NODES, C2, F1);
    }
    attn2_kernel<<<(N_NODES * 32 + 255) / 256, 256>>>(a_src2, a_dst2);
    gat2_kernel<<<(N_NODES + 7) / 8, 256>>>(b2);

    // MLP head
    mlp_kernel<<<NUM_GRAPHS, 192>>>(fc1_w, fc1_b, fc2_w, fc2_b, out);
}

// round 4
// speedup vs baseline: 2.0293x; 1.1462x over previous
#include <cuda_runtime.h>
#include <math.h>

#define N_NODES 100000
#define NUM_GRAPHS 128
#define H1 4
#define C1 48
#define F1 192   // H1*C1
#define C2 96
#define D_IN 128
#define NEG_SLOPE 0.2f
#define E_MAX 1750000   // raw edges (1.6M) + self loops (100k) with slack

// ---------------- scratch (device globals; no allocation) ----------------
__device__ float g_h1[N_NODES * F1];      // x @ W1
__device__ float g_h1r[N_NODES * F1];     // layer1 output (relu'd)
__device__ float g_asrc1[N_NODES * H1];
__device__ float g_adst1[N_NODES * H1];
__device__ float g_h2[N_NODES * C2];      // h1r @ W2
__device__ float g_asrc2[N_NODES];
__device__ float g_adst2[N_NODES];
__device__ float g_pool[NUM_GRAPHS * C2];
__device__ float g_cnt[NUM_GRAPHS];
__device__ int g_src[E_MAX];
__device__ int g_dst[E_MAX];
__device__ int g_batch[N_NODES];
__device__ int g_is64;
// CSR (sorted by dst)
__device__ int g_deg[N_NODES];
__device__ int g_off[N_NODES + 1];
__device__ int g_cur[N_NODES];
__device__ int g_csr_src[E_MAX];
__device__ float g_p[E_MAX * H1];         // per-edge exp scores

__device__ __forceinline__ float leaky(float s) {
    return s > 0.0f ? s : NEG_SLOPE * s;
}

// ---------------- init (zero counters only) ----------------
__global__ void init_kernel() {
    int i = blockIdx.x * blockDim.x + threadIdx.x;
    int stride = gridDim.x * blockDim.x;
    for (int k = i; k < N_NODES; k += stride) g_deg[k] = 0;
    for (int k = i; k < NUM_GRAPHS * C2; k += stride) g_pool[k] = 0.0f;
    for (int k = i; k < NUM_GRAPHS; k += stride) g_cnt[k] = 0.0f;
}

// ---------------- dtype sniff: int64 vs int32 index buffers ----------------
__global__ void sniff_kernel(const unsigned int* __restrict__ w) {
    __shared__ int any_nonzero;
    if (threadIdx.x == 0) any_nonzero = 0;
    __syncthreads();
    for (int i = threadIdx.x; i < 256; i += blockDim.x) {
        if (w[2 * i + 1] != 0u) any_nonzero = 1;
    }
    __syncthreads();
    if (threadIdx.x == 0) g_is64 = (any_nonzero == 0) ? 1 : 0;
}

// decode edge_index + self loops into int32 arrays; fused degree histogram
__global__ void decode_edges(const void* __restrict__ ei_raw, int E0) {
    int e = blockIdx.x * blockDim.x + threadIdx.x;
    int Etot = E0 + N_NODES;
    if (e >= Etot) return;
    int src, dst;
    if (e < E0) {
        if (g_is64) {
            const long long* p = (const long long*)ei_raw;
            src = (int)p[e];
            dst = (int)p[E0 + e];
        } else {
            const int* p = (const int*)ei_raw;
            src = p[e];
            dst = p[E0 + e];
        }
    } else {
        src = dst = e - E0;  // self loop
    }
    g_src[e] = src;
    g_dst[e] = dst;
    atomicAdd(&g_deg[dst], 1);
}

// batch is sorted: each block spans 1-2 graphs -> smem histogram, few global atomics
__global__ void decode_batch(const void* __restrict__ b_raw) {
    __shared__ int hist[NUM_GRAPHS];
    for (int i = threadIdx.x; i < NUM_GRAPHS; i += blockDim.x) hist[i] = 0;
    __syncthreads();
    int n = blockIdx.x * blockDim.x + threadIdx.x;
    if (n < N_NODES) {
        int b = g_is64 ? (int)((const long long*)b_raw)[n] : ((const int*)b_raw)[n];
        g_batch[n] = b;
        atomicAdd(&hist[b], 1);
    }
    __syncthreads();
    for (int i = threadIdx.x; i < NUM_GRAPHS; i += blockDim.x)
        if (hist[i]) atomicAdd(&g_cnt[i], (float)hist[i]);
}

// ---------------- single-block exclusive scan over degrees ----------------
__global__ void scan_kernel() {
    __shared__ int part[1024];
    int t = threadIdx.x;
    const int CH = (N_NODES + 1023) / 1024;
    int lo = t * CH, hi = min(lo + CH, N_NODES);
    int s = 0;
    for (int i = lo; i < hi; i++) s += g_deg[i];
    part[t] = s;
    __syncthreads();
    for (int o = 1; o < 1024; o <<= 1) {
        int v = (t >= o) ? part[t - o] : 0;
        __syncthreads();
        part[t] += v;
        __syncthreads();
    }
    int base = (t > 0) ? part[t - 1] : 0;
    for (int i = lo; i < hi; i++) {
        g_off[i] = base;
        g_cur[i] = base;
        base += g_deg[i];
    }
    if (t == 1023) g_off[N_NODES] = part[1023];
}

__global__ void scatter_kernel(int Etot) {
    int e = blockIdx.x * blockDim.x + threadIdx.x;
    if (e >= Etot) return;
    int pos = atomicAdd(&g_cur[g_dst[e]], 1);
    g_csr_src[pos] = g_src[e];
}

// ---------------- high-efficiency SGEMM: 8x4 microtile, float4 everywhere ----
// C[M,N] = A[M,K] @ B[K,N], row-major. BM*BN == 8192 (256 threads * 32 outputs),
// BN must divide N, K must be a multiple of TBK (32).
template <int TBM, int TBN>
__global__ void __launch_bounds__(256) sgemm_kernel(const float* __restrict__ A,
                                                    const float* __restrict__ B,
                                                    float* __restrict__ C,
                                                    int M, int N, int K) {
    const int TBK = 32;
    __shared__ float As[TBK][TBM + 4];  // transposed A tile, padded
    __shared__ float Bs[TBK][TBN + 4];

    int tid = threadIdx.x;
    int row0 = blockIdx.y * TBM;
    int col0 = blockIdx.x * TBN;
    int tx = tid % (TBN / 4);   // output col group (4 cols)
    int ty = tid / (TBN / 4);   // output row group (8 rows)

    float acc[8][4];
#pragma unroll
    for (int i = 0; i < 8; i++)
#pragma unroll
        for (int j = 0; j < 4; j++) acc[i][j] = 0.0f;

    const int A_F4 = TBM * TBK / 4;   // float4 count per A tile
    const int B_F4 = TBK * TBN / 4;

    for (int k0 = 0; k0 < K; k0 += TBK) {
        // load A tile (transposed into As)
#pragma unroll
        for (int it = 0; it < A_F4 / 256; it++) {
            int idA = tid + it * 256;
            int kc = idA % (TBK / 4);
            int r = idA / (TBK / 4);
            int gr = row0 + r;
            float4 v = (gr < M) ? *(const float4*)&A[(size_t)gr * K + k0 + kc * 4]
                                : make_float4(0.f, 0.f, 0.f, 0.f);
            As[kc * 4 + 0][r] = v.x;
            As[kc * 4 + 1][r] = v.y;
            As[kc * 4 + 2][r] = v.z;
            As[kc * 4 + 3][r] = v.w;
        }
        // load B tile
#pragma unroll
        for (int it = 0; it < B_F4 / 256; it++) {
            int idB = tid + it * 256;
            int c4 = idB % (TBN / 4);
            int r = idB / (TBN / 4);
            *(float4*)&Bs[r][c4 * 4] = *(const float4*)&B[(size_t)(k0 + r) * N + col0 + c4 * 4];
        }
        __syncthreads();

#pragma unroll
        for (int k = 0; k < TBK; k++) {
            float4 a0 = *(const float4*)&As[k][ty * 8];
            float4 a1 = *(const float4*)&As[k][ty * 8 + 4];
            float4 b = *(const float4*)&Bs[k][tx * 4];
            float av[8] = {a0.x, a0.y, a0.z, a0.w, a1.x, a1.y, a1.z, a1.w};
            float bv[4] = {b.x, b.y, b.z, b.w};
#pragma unroll
            for (int i = 0; i < 8; i++)
#pragma unroll
                for (int j = 0; j < 4; j++) acc[i][j] += av[i] * bv[j];
        }
        __syncthreads();
    }

#pragma unroll
    for (int i = 0; i < 8; i++) {
        int gr = row0 + ty * 8 + i;
        if (gr < M) {
            float4 v = make_float4(acc[i][0], acc[i][1], acc[i][2], acc[i][3]);
            *(float4*)&C[(size_t)gr * N + col0 + tx * 4] = v;
        }
    }
}

// ---------------- attention scalars ----------------
__global__ void attn1_kernel(const float* __restrict__ a_src, const float* __restrict__ a_dst) {
    int idx = blockIdx.x * blockDim.x + threadIdx.x;  // node*4 + head
    if (idx >= N_NODES * H1) return;
    int n = idx >> 2, h = idx & 3;
    const float* hp = &g_h1[(size_t)n * F1 + h * C1];
    const float* ws = &a_src[h * C1];
    const float* wd = &a_dst[h * C1];
    float ss = 0.0f, sd = 0.0f;
#pragma unroll
    for (int j = 0; j < C1; j++) {
        float v = hp[j];
        ss += v * ws[j];
        sd += v * wd[j];
    }
    g_asrc1[idx] = ss;
    g_adst1[idx] = sd;
}

__global__ void attn2_kernel(const float* __restrict__ a_src, const float* __restrict__ a_dst) {
    int w = (blockIdx.x * blockDim.x + threadIdx.x) >> 5;
    int lane = threadIdx.x & 31;
    if (w >= N_NODES) return;
    const float* hp = &g_h2[(size_t)w * C2];
    float ss = 0.0f, sd = 0.0f;
#pragma unroll
    for (int k = 0; k < 3; k++) {
        int j = lane + 32 * k;
        float v = hp[j];
        ss += v * a_src[j];
        sd += v * a_dst[j];
    }
#pragma unroll
    for (int o = 16; o > 0; o >>= 1) {
        ss += __shfl_down_sync(0xffffffffu, ss, o);
        sd += __shfl_down_sync(0xffffffffu, sd, o);
    }
    if (lane == 0) {
        g_asrc2[w] = ss;
        g_adst2[w] = sd;
    }
}

// ---------------- layer 1 fused: softmax + aggregate + bias + relu (warp/node) ----------------
__global__ void gat1_kernel(const float* __restrict__ b1) {
    int node = (blockIdx.x * blockDim.x + threadIdx.x) >> 5;
    int lane = threadIdx.x & 31;
    if (node >= N_NODES) return;
    int start = g_off[node], end = g_off[node + 1];

    float4 ad = *(const float4*)&g_adst1[node * H1];

    // pass A: exp scores + denominator
    float4 den = make_float4(0.f, 0.f, 0.f, 0.f);
    for (int idx = start + lane; idx < end; idx += 32) {
        int src = g_csr_src[idx];
        float4 as = *(const float4*)&g_asrc1[src * H1];
        float4 p;
        p.x = __expf(leaky(as.x + ad.x));
        p.y = __expf(leaky(as.y + ad.y));
        p.z = __expf(leaky(as.z + ad.z));
        p.w = __expf(leaky(as.w + ad.w));
        *(float4*)&g_p[(size_t)idx * 4] = p;
        den.x += p.x; den.y += p.y; den.z += p.z; den.w += p.w;
    }
#pragma unroll
    for (int o = 16; o > 0; o >>= 1) {
        den.x += __shfl_xor_sync(0xffffffffu, den.x, o);
        den.y += __shfl_xor_sync(0xffffffffu, den.y, o);
        den.z += __shfl_xor_sync(0xffffffffu, den.z, o);
        den.w += __shfl_xor_sync(0xffffffffu, den.w, o);
    }
    float inv0 = 1.0f / den.x, inv1 = 1.0f / den.y, inv2 = 1.0f / den.z, inv3 = 1.0f / den.w;

    // pass B: weighted aggregation
    float acc[6] = {0.f, 0.f, 0.f, 0.f, 0.f, 0.f};
    for (int idx = start; idx < end; idx++) {
        int src = g_csr_src[idx];                           // broadcast load
        float4 p4 = *(const float4*)&g_p[(size_t)idx * 4];  // broadcast load
        float a0 = p4.x * inv0, a1 = p4.y * inv1, a2 = p4.z * inv2, a3 = p4.w * inv3;
        const float* hp = &g_h1[(size_t)src * F1];
#pragma unroll
        for (int k = 0; k < 6; k++) {
            int c = k * 32 + lane;
            float al = (c < 48) ? a0 : (c < 96) ? a1 : (c < 144) ? a2 : a3;
            acc[k] += hp[c] * al;
        }
    }
#pragma unroll
    for (int k = 0; k < 6; k++) {
        int c = k * 32 + lane;
        g_h1r[(size_t)node * F1 + c] = fmaxf(acc[k] + b1[c], 0.0f);
    }
}

// ---------------- layer 2 fused: softmax + aggregate + bias + relu + pool (warp/node) ----------------
__global__ void gat2_kernel(const float* __restrict__ b2) {
    int node = (blockIdx.x * blockDim.x + threadIdx.x) >> 5;
    int lane = threadIdx.x & 31;
    if (node >= N_NODES) return;
    int start = g_off[node], end = g_off[node + 1];

    float ad = g_adst2[node];
    float den = 0.0f;
    for (int idx = start + lane; idx < end; idx += 32) {
        int src = g_csr_src[idx];
        float p = __expf(leaky(g_asrc2[src] + ad));
        g_p[idx] = p;
        den += p;
    }
#pragma unroll
    for (int o = 16; o > 0; o >>= 1) den += __shfl_xor_sync(0xffffffffu, den, o);
    float inv = 1.0f / den;

    float acc[3] = {0.f, 0.f, 0.f};
    for (int idx = start; idx < end; idx++) {
        int src = g_csr_src[idx];
        float alpha = g_p[idx] * inv;
        const float* hp = &g_h2[(size_t)src * C2];
#pragma unroll
        for (int k = 0; k < 3; k++) acc[k] += hp[k * 32 + lane] * alpha;
    }
    int gp = g_batch[node] * C2;
#pragma unroll
    for (int k = 0; k < 3; k++) {
        int c = k * 32 + lane;
        float v = fmaxf(acc[k] + b2[c], 0.0f);
        atomicAdd(&g_pool[gp + c], v);
    }
}

// ---------------- final MLP: one block per graph ----------------
__global__ void mlp_kernel(const float* __restrict__ fc1_w, const float* __restrict__ fc1_b,
                           const float* __restrict__ fc2_w, const float* __restrict__ fc2_b,
                           float* __restrict__ out) {
    __shared__ float p[C2];
    __shared__ float z[192];
    int g = blockIdx.x;
    int t = threadIdx.x;  // 192 threads
    float inv = 1.0f / fmaxf(g_cnt[g], 1.0f);
    if (t < C2) p[t] = g_pool[g * C2 + t] * inv;
    __syncthreads();
    float acc = fc1_b[t];
#pragma unroll
    for (int k = 0; k < C2; k++) acc += p[k] * fc1_w[k * 192 + t];
    z[t] = fmaxf(acc, 0.0f);
    __syncthreads();
    if (t < C2) {
        float o = fc2_b[t];
#pragma unroll
        for (int k = 0; k < 192; k++) o += z[k] * fc2_w[k * C2 + t];
        out[g * C2 + t] = o;
    }
}

// ---------------- host launch ----------------
extern "C" void kernel_launch(void* const* d_in, const int* in_sizes, int n_in,
                              void* d_out, int out_size) {
    const float* x = (const float*)d_in[0];
    const void* ei_raw = d_in[1];
    const void* batch_raw = d_in[2];
    const float* W1 = (const float*)d_in[3];
    const float* a_src1 = (const float*)d_in[4];
    const float* a_dst1 = (const float*)d_in[5];
    const float* b1 = (const float*)d_in[6];
    const float* W2 = (const float*)d_in[7];
    const float* a_src2 = (const float*)d_in[8];
    const float* a_dst2 = (const float*)d_in[9];
    const float* b2 = (const float*)d_in[10];
    const float* fc1_w = (const float*)d_in[11];
    const float* fc1_b = (const float*)d_in[12];
    const float* fc2_w = (const float*)d_in[13];
    const float* fc2_b = (const float*)d_in[14];
    float* out = (float*)d_out;

    int E0 = in_sizes[1] / 2;
    int Etot = E0 + N_NODES;

    float *h1p, *h1rp, *h2p;
    cudaGetSymbolAddress((void**)&h1p, g_h1);
    cudaGetSymbolAddress((void**)&h1rp, g_h1r);
    cudaGetSymbolAddress((void**)&h2p, g_h2);

    // graph preprocessing
    init_kernel<<<256, 256>>>();
    sniff_kernel<<<1, 256>>>((const unsigned int*)ei_raw);
    decode_edges<<<(Etot + 255) / 256, 256>>>(ei_raw, E0);
    decode_batch<<<(N_NODES + 255) / 256, 256>>>(batch_raw);
    scan_kernel<<<1, 1024>>>();
    scatter_kernel<<<(Etot + 255) / 256, 256>>>(Etot);

    // layer 1: [100000,128] @ [128,192]
    {
        dim3 grid(F1 / 64, (N_NODES + 127) / 128);
        sgemm_kernel<128, 64><<<grid, 256>>>(x, W1, h1p, N_NODES, F1, D_IN);
    }
    attn1_kernel<<<(N_NODES * H1 + 255) / 256, 256>>>(a_src1, a_dst1);
    gat1_kernel<<<(N_NODES + 7) / 8, 256>>>(b1);

    // layer 2: [100000,192] @ [192,96]
    {
        dim3 grid(C2 / 32, (N_NODES + 255) / 256);
        sgemm_kernel<256, 32><<<grid, 256>>>(h1rp, W2, h2p, N_NODES, C2, F1);
    }
    attn2_kernel<<<(N_NODES * 32 + 255) / 256, 256>>>(a_src2, a_dst2);
    gat2_kernel<<<(N_NODES + 7) / 8, 256>>>(b2);

    // MLP head
    mlp_kernel<<<NUM_GRAPHS, 192>>>(fc1_w, fc1_b, fc2_w, fc2_b, out);
}